// round 15
// baseline (speedup 1.0000x reference)
#include <cuda_runtime.h>
#include <cuda_fp16.h>
#include <math.h>

#define AST   112                     // bytes per row: 48 halves (96B) + 16 pad
#define AWARP (32 * AST)              // 3584
#define AREG  (8 * AWARP)             // 28672
#define BREG  (256 * AST)             // 28672
#define VOFF  (AREG + BREG)           // float v[256]
#define COFF  (VOFF + 1024)           // float sC[16]
#define SMTOT (COFF + 64)

typedef unsigned int u32;
extern __shared__ char dynsm[];

#define MMA(D, a0, a1, a2, a3, b0, b1) asm volatile( \
    "mma.sync.aligned.m16n8k16.row.col.f32.f16.f16.f32 " \
    "{%0,%1,%2,%3},{%4,%5,%6,%7},{%8,%9},{%0,%1,%2,%3};" \
    : "+f"((D)[0]), "+f"((D)[1]), "+f"((D)[2]), "+f"((D)[3]) \
    : "r"(a0), "r"(a1), "r"(a2), "r"(a3), "r"(b0), "r"(b1))

__global__ __launch_bounds__(256, 2)
void gmm_mma(const float4* __restrict__ samples4,
             const float* __restrict__ Phi,
             const float* __restrict__ mu,
             const float* __restrict__ Sigma,
             float* __restrict__ out, int N) {
    char*  smA = dynsm;
    char*  smB = dynsm + AREG;
    float* vf  = (float*)(dynsm + VOFF);
    float* sC  = (float*)(dynsm + COFF);

    const int tid = threadIdx.x, wid = tid >> 5, lane = tid & 31;
    const int g = lane >> 2, t = lane & 3;

    // ---- Prologue: Cholesky + L^{-1}; scratch overlays smA+smB (34.8KB) ----
    float* sL  = (float*)dynsm;          // [16] x [16][17]
    float* sMi = sL + 16 * 272;
    const int k2 = wid * 2 + (lane >> 4);
    const int r  = lane & 15;
    float mrow[16], vv = 0.f, cnorm = 0.f;
    {
        float* L  = sL  + k2 * 272;
        float* Mi = sMi + k2 * 272;
        for (int j = 0; j < 16; j++) L[r * 17 + j] = Sigma[(k2 * 16 + r) * 16 + j];
        __syncwarp();
        for (int p = 0; p < 16; p++) {
            if (r == p) {
                float s = L[p * 17 + p];
                for (int q = 0; q < p; q++) s -= L[p * 17 + q] * L[p * 17 + q];
                L[p * 17 + p] = sqrtf(s);
            }
            __syncwarp();
            if (r > p) {
                float s = L[r * 17 + p];
                for (int q = 0; q < p; q++) s -= L[r * 17 + q] * L[p * 17 + q];
                L[r * 17 + p] = s / L[p * 17 + p];
            }
            __syncwarp();
        }
        {
            int c = r;
            for (int i = 0; i < c; i++) Mi[i * 17 + c] = 0.f;
            Mi[c * 17 + c] = 1.f / L[c * 17 + c];
            for (int i = c + 1; i < 16; i++) {
                float s = 0.f;
                for (int q = c; q < i; q++) s += L[i * 17 + q] * Mi[q * 17 + c];
                Mi[i * 17 + c] = -s / L[i * 17 + i];
            }
        }
        __syncwarp();
        for (int j = 0; j < 16; j++) mrow[j] = (j <= r) ? Mi[r * 17 + j] : 0.f;
        for (int j = 0; j <= r; j++) vv += mrow[j] * mu[k2 * 16 + j];
        float prodL = 1.f;
        for (int i = 0; i < 16; i++) prodL *= L[i * 17 + i];
        cnorm = Phi[k2] / (sqrtf(2.f * 3.14159265358979323846f) * prodL);
    }
    __syncthreads();

    // ---- Write B row n = 16*k2 + r: [Mhi(0:16) | Mhi(16:32) | Mlo(32:48)] ----
    {
        char* br = smB + (k2 * 16 + r) * AST;
        for (int j = 0; j < 16; j++) {
            __half h = __float2half_rn(mrow[j]);
            __half l = __float2half_rn(mrow[j] - __half2float(h));
            *(__half*)(br + 2 * j)        = h;
            *(__half*)(br + 2 * (16 + j)) = h;
            *(__half*)(br + 2 * (32 + j)) = l;
        }
        vf[k2 * 16 + r] = vv;            // exact fp32; folded into D init
        if (r == 0) sC[k2] = cnorm;
    }
    __syncthreads();

    // ---- Main loop: 32 samples per warp-tile ----
    const int tiles = (N + 31) >> 5;
    for (int tt = blockIdx.x * 8 + wid; tt < tiles; tt += gridDim.x * 8) {
        long s0 = (long)tt << 5;
        {   // stage sample s0+lane: A row = [xhi | xlo | xhi]
            long sl = s0 + lane; if (sl > N - 1) sl = N - 1;
            const float4* sp = samples4 + sl * 4;
            float4 q0 = sp[0], q1 = sp[1], q2 = sp[2], q3 = sp[3];
            float x[16] = {q0.x,q0.y,q0.z,q0.w, q1.x,q1.y,q1.z,q1.w,
                           q2.x,q2.y,q2.z,q2.w, q3.x,q3.y,q3.z,q3.w};
            char* ar = smA + wid * AWARP + lane * AST;
            #pragma unroll
            for (int j = 0; j < 8; j++) {
                __half2 h2 = __floats2half2_rn(x[2*j], x[2*j+1]);
                float2  hf = __half22float2(h2);
                __half2 l2 = __floats2half2_rn(x[2*j] - hf.x, x[2*j+1] - hf.y);
                *(__half2*)(ar + 4 * j)      = h2;   // k = 2j
                *(__half2*)(ar + 64 + 4 * j) = h2;   // k = 32+2j
                *(__half2*)(ar + 32 + 4 * j) = l2;   // k = 16+2j
            }
        }
        __syncwarp();

        #pragma unroll
        for (int T = 0; T < 2; T++) {
            u32 a[3][4];
            #pragma unroll
            for (int c = 0; c < 3; c++) {
                const char* ap = smA + wid * AWARP + (T * 16 + g) * AST
                               + c * 32 + t * 4;
                a[c][0] = *(const u32*)ap;
                a[c][1] = *(const u32*)(ap + 8 * AST);
                a[c][2] = *(const u32*)(ap + 16);
                a[c][3] = *(const u32*)(ap + 8 * AST + 16);
            }
            float p0 = 0.f, p1 = 0.f;
            #pragma unroll
            for (int m = 0; m < 16; m++) {
                const char* bp = smB + (m * 16 + g) * AST + t * 4;
                float2 v0 = *(const float2*)(vf + m * 16 + 2 * t);
                float2 v1 = *(const float2*)(vf + m * 16 + 8 + 2 * t);
                float D0[4] = {-v0.x, -v0.y, -v0.x, -v0.y};
                float D1[4] = {-v1.x, -v1.y, -v1.x, -v1.y};
                #pragma unroll
                for (int c = 0; c < 3; c++) {
                    u32 b00 = *(const u32*)(bp + c * 32);
                    u32 b01 = *(const u32*)(bp + c * 32 + 16);
                    MMA(D0, a[c][0], a[c][1], a[c][2], a[c][3], b00, b01);
                    u32 b10 = *(const u32*)(bp + 8 * AST + c * 32);
                    u32 b11 = *(const u32*)(bp + 8 * AST + c * 32 + 16);
                    MMA(D1, a[c][0], a[c][1], a[c][2], a[c][3], b10, b11);
                }
                float q0 = D0[0]*D0[0] + D0[1]*D0[1] + D1[0]*D1[0] + D1[1]*D1[1];
                float q1 = D0[2]*D0[2] + D0[3]*D0[3] + D1[2]*D1[2] + D1[3]*D1[3];
                q0 += __shfl_xor_sync(0xffffffffu, q0, 1);
                q0 += __shfl_xor_sync(0xffffffffu, q0, 2);
                q1 += __shfl_xor_sync(0xffffffffu, q1, 1);
                q1 += __shfl_xor_sync(0xffffffffu, q1, 2);
                float ck = sC[m];
                p0 += ck * __expf(-0.5f * q0);
                p1 += ck * __expf(-0.5f * q1);
            }
            if (t == 0) {
                long so = s0 + T * 16 + g;
                if (so < N)     out[so]     = -__logf(p0);
                if (so + 8 < N) out[so + 8] = -__logf(p1);
            }
        }
    }
}

// ---------------------------------------------------------------------------
extern "C" void kernel_launch(void* const* d_in, const int* in_sizes, int n_in,
                              void* d_out, int out_size) {
    const float* samples = (const float*)d_in[0];
    const float* Phi     = (const float*)d_in[1];
    const float* mu      = (const float*)d_in[2];
    const float* Sigma   = (const float*)d_in[3];
    int N = in_sizes[0] / 16;

    cudaFuncSetAttribute(gmm_mma, cudaFuncAttributeMaxDynamicSharedMemorySize,
                         SMTOT);
    gmm_mma<<<296, 256, SMTOT>>>((const float4*)samples, Phi, mu, Sigma,
                                 (float*)d_out, N);
}

// round 16
// speedup vs baseline: 2.3125x; 2.3125x over previous
#include <cuda_runtime.h>
#include <cuda_fp16.h>
#include <math.h>

#define AST   112                     // bytes per row: 48 halves (96B) + 16 pad
#define AWARP (32 * AST)              // 3584
#define AREG  (8 * AWARP)             // 28672
#define BREG  (256 * AST)             // 28672
#define VOFF  (AREG + BREG)           // float v[256]
#define COFF  (VOFF + 1024)           // float sC[16]
#define SMTOT (COFF + 64)

typedef unsigned int u32;
extern __shared__ char dynsm[];

#define MMA(D, a0, a1, a2, a3, b0, b1) asm volatile( \
    "mma.sync.aligned.m16n8k16.row.col.f32.f16.f16.f32 " \
    "{%0,%1,%2,%3},{%4,%5,%6,%7},{%8,%9},{%0,%1,%2,%3};" \
    : "+f"((D)[0]), "+f"((D)[1]), "+f"((D)[2]), "+f"((D)[3]) \
    : "r"(a0), "r"(a1), "r"(a2), "r"(a3), "r"(b0), "r"(b1))

__global__ __launch_bounds__(256, 1)
void gmm_mma(const float4* __restrict__ samples4,
             const float* __restrict__ Phi,
             const float* __restrict__ mu,
             const float* __restrict__ Sigma,
             float* __restrict__ out, int N) {
    char*  smA = dynsm;
    char*  smB = dynsm + AREG;
    float* vf  = (float*)(dynsm + VOFF);
    float* sC  = (float*)(dynsm + COFF);

    const int tid = threadIdx.x, wid = tid >> 5, lane = tid & 31;
    const int g = lane >> 2, t = lane & 3;

    // ---- Prologue: Cholesky + L^{-1}; scratch overlays smA+smB ----
    float* sL  = (float*)dynsm;          // [16] x [16][17]
    float* sMi = sL + 16 * 272;
    const int k2 = wid * 2 + (lane >> 4);
    const int r  = lane & 15;
    float mrow[16], vv = 0.f, cnorm = 0.f;
    {
        float* L  = sL  + k2 * 272;
        float* Mi = sMi + k2 * 272;
        for (int j = 0; j < 16; j++) L[r * 17 + j] = Sigma[(k2 * 16 + r) * 16 + j];
        __syncwarp();
        for (int p = 0; p < 16; p++) {
            if (r == p) {
                float s = L[p * 17 + p];
                for (int q = 0; q < p; q++) s -= L[p * 17 + q] * L[p * 17 + q];
                L[p * 17 + p] = sqrtf(s);
            }
            __syncwarp();
            if (r > p) {
                float s = L[r * 17 + p];
                for (int q = 0; q < p; q++) s -= L[r * 17 + q] * L[p * 17 + q];
                L[r * 17 + p] = s / L[p * 17 + p];
            }
            __syncwarp();
        }
        {
            int c = r;
            for (int i = 0; i < c; i++) Mi[i * 17 + c] = 0.f;
            Mi[c * 17 + c] = 1.f / L[c * 17 + c];
            for (int i = c + 1; i < 16; i++) {
                float s = 0.f;
                for (int q = c; q < i; q++) s += L[i * 17 + q] * Mi[q * 17 + c];
                Mi[i * 17 + c] = -s / L[i * 17 + i];
            }
        }
        __syncwarp();
        for (int j = 0; j < 16; j++) mrow[j] = (j <= r) ? Mi[r * 17 + j] : 0.f;
        for (int j = 0; j <= r; j++) vv += mrow[j] * mu[k2 * 16 + j];
        float prodL = 1.f;
        for (int i = 0; i < 16; i++) prodL *= L[i * 17 + i];
        cnorm = Phi[k2] / (sqrtf(2.f * 3.14159265358979323846f) * prodL);
    }
    __syncthreads();

    // ---- Write B row n = 16*k2 + r: [Mhi(0:16) | Mhi(16:32) | Mlo(32:48)] ----
    {
        char* br = smB + (k2 * 16 + r) * AST;
        for (int j = 0; j < 16; j++) {
            __half h = __float2half_rn(mrow[j]);
            __half l = __float2half_rn(mrow[j] - __half2float(h));
            *(__half*)(br + 2 * j)        = h;
            *(__half*)(br + 2 * (16 + j)) = h;
            *(__half*)(br + 2 * (32 + j)) = l;
        }
        vf[k2 * 16 + r] = vv;            // exact fp32; folded into D init
        if (r == 0) sC[k2] = cnorm;
    }
    __syncthreads();

    // ---- Main loop: 32 samples per warp-tile ----
    const int tiles = (N + 31) >> 5;
    for (int tt = blockIdx.x * 8 + wid; tt < tiles; tt += gridDim.x * 8) {
        long s0 = (long)tt << 5;
        {   // stage sample s0+lane: A row = [xhi | xlo | xhi]
            long sl = s0 + lane; if (sl > N - 1) sl = N - 1;
            const float4* sp = samples4 + sl * 4;
            float4 q0 = sp[0], q1 = sp[1], q2 = sp[2], q3 = sp[3];
            float x[16] = {q0.x,q0.y,q0.z,q0.w, q1.x,q1.y,q1.z,q1.w,
                           q2.x,q2.y,q2.z,q2.w, q3.x,q3.y,q3.z,q3.w};
            char* ar = smA + wid * AWARP + lane * AST;
            #pragma unroll
            for (int j = 0; j < 8; j++) {
                __half2 h2 = __floats2half2_rn(x[2*j], x[2*j+1]);
                float2  hf = __half22float2(h2);
                __half2 l2 = __floats2half2_rn(x[2*j] - hf.x, x[2*j+1] - hf.y);
                *(__half2*)(ar + 4 * j)      = h2;   // k = 2j
                *(__half2*)(ar + 64 + 4 * j) = h2;   // k = 32+2j
                *(__half2*)(ar + 32 + 4 * j) = l2;   // k = 16+2j
            }
        }
        __syncwarp();

        // a-fragments for both T tiles, all 3 K-chunks (24 regs).
        u32 a[2][3][4];
        #pragma unroll
        for (int T = 0; T < 2; T++)
            #pragma unroll
            for (int c = 0; c < 3; c++) {
                const char* ap = smA + wid * AWARP + (T * 16 + g) * AST
                               + c * 32 + t * 4;
                a[T][c][0] = *(const u32*)ap;
                a[T][c][1] = *(const u32*)(ap + 8 * AST);
                a[T][c][2] = *(const u32*)(ap + 16);
                a[T][c][3] = *(const u32*)(ap + 8 * AST + 16);
            }

        float p00 = 0.f, p01 = 0.f, p10 = 0.f, p11 = 0.f;
        #pragma unroll
        for (int m = 0; m < 16; m++) {
            // B fragments + v-init: loaded ONCE (T-independent).
            const char* bp = smB + (m * 16 + g) * AST + t * 4;
            u32 b[3][4];
            #pragma unroll
            for (int c = 0; c < 3; c++) {
                b[c][0] = *(const u32*)(bp + c * 32);
                b[c][1] = *(const u32*)(bp + c * 32 + 16);
                b[c][2] = *(const u32*)(bp + 8 * AST + c * 32);
                b[c][3] = *(const u32*)(bp + 8 * AST + c * 32 + 16);
            }
            float2 v0 = *(const float2*)(vf + m * 16 + 2 * t);
            float2 v1 = *(const float2*)(vf + m * 16 + 8 + 2 * t);
            float ck = sC[m];

            #pragma unroll
            for (int T = 0; T < 2; T++) {
                float D0[4] = {-v0.x, -v0.y, -v0.x, -v0.y};
                float D1[4] = {-v1.x, -v1.y, -v1.x, -v1.y};
                #pragma unroll
                for (int c = 0; c < 3; c++) {
                    MMA(D0, a[T][c][0], a[T][c][1], a[T][c][2], a[T][c][3],
                        b[c][0], b[c][1]);
                    MMA(D1, a[T][c][0], a[T][c][1], a[T][c][2], a[T][c][3],
                        b[c][2], b[c][3]);
                }
                float q0 = D0[0]*D0[0] + D0[1]*D0[1] + D1[0]*D1[0] + D1[1]*D1[1];
                float q1 = D0[2]*D0[2] + D0[3]*D0[3] + D1[2]*D1[2] + D1[3]*D1[3];
                q0 += __shfl_xor_sync(0xffffffffu, q0, 1);
                q0 += __shfl_xor_sync(0xffffffffu, q0, 2);
                q1 += __shfl_xor_sync(0xffffffffu, q1, 1);
                q1 += __shfl_xor_sync(0xffffffffu, q1, 2);
                float e0 = ck * __expf(-0.5f * q0);
                float e1 = ck * __expf(-0.5f * q1);
                if (T == 0) { p00 += e0; p01 += e1; }
                else        { p10 += e0; p11 += e1; }
            }
        }

        if (t == 0) {
            long so = s0 + g;
            if (so < N)      out[so]      = -__logf(p00);
            if (so + 8 < N)  out[so + 8]  = -__logf(p01);
            if (so + 16 < N) out[so + 16] = -__logf(p10);
            if (so + 24 < N) out[so + 24] = -__logf(p11);
        }
    }
}

// ---------------------------------------------------------------------------
extern "C" void kernel_launch(void* const* d_in, const int* in_sizes, int n_in,
                              void* d_out, int out_size) {
    const float* samples = (const float*)d_in[0];
    const float* Phi     = (const float*)d_in[1];
    const float* mu      = (const float*)d_in[2];
    const float* Sigma   = (const float*)d_in[3];
    int N = in_sizes[0] / 16;

    cudaFuncSetAttribute(gmm_mma, cudaFuncAttributeMaxDynamicSharedMemorySize,
                         SMTOT);
    gmm_mma<<<148, 256, SMTOT>>>((const float4*)samples, Phi, mu, Sigma,
                                 (float*)d_out, N);
}